// round 4
// baseline (speedup 1.0000x reference)
#include <cuda_runtime.h>
#include <math_constants.h>
#include <cstdint>

#define S_LEN 8192
#define D_IN  512
#define D_OUT 64

#define CHUNK_TILES 16          // key tiles (of 64) per chunk CTA
#define MAX_CHUNKS  8           // ceil(128 / 16)
#define SMS 68                  // smem row stride (words)

// Scratch (device globals: no allocation in kernel_launch)
__device__ float g_Q[S_LEN * D_OUT];
__device__ float g_K[S_LEN * D_OUT];
__device__ float g_V[S_LEN * D_OUT];
// split-K partials: per (qblk, chunk): unnormalized O[64][64], m[64], l[64]
__device__ float g_Op[128 * MAX_CHUNKS * 64 * 64];
__device__ float g_m [128 * MAX_CHUNKS * 64];
__device__ float g_l [128 * MAX_CHUNKS * 64];

// ---------------------------------------------------------------------------
// tf32 mma.sync helpers
// ---------------------------------------------------------------------------
__device__ __forceinline__ uint32_t f2tf32(float x) {
    uint32_t r;
    asm("cvt.rna.tf32.f32 %0, %1;" : "=r"(r) : "f"(x));
    return r;
}

__device__ __forceinline__ float fast_ex2(float x) {
    float y;
    asm("ex2.approx.ftz.f32 %0, %1;" : "=f"(y) : "f"(x));
    return y;
}

__device__ __forceinline__ void mma_tf32(
    float& d0, float& d1, float& d2, float& d3,
    uint32_t a0, uint32_t a1, uint32_t a2, uint32_t a3,
    uint32_t b0, uint32_t b1)
{
    asm volatile(
        "mma.sync.aligned.m16n8k8.row.col.f32.tf32.tf32.f32 "
        "{%0,%1,%2,%3}, {%4,%5,%6,%7}, {%8,%9}, {%0,%1,%2,%3};\n"
        : "+f"(d0), "+f"(d1), "+f"(d2), "+f"(d3)
        : "r"(a0), "r"(a1), "r"(a2), "r"(a3), "r"(b0), "r"(b1));
}

// ---------------------------------------------------------------------------
// Kernel 1: QKV projection via tf32 tensor cores.
// C = X @ W^T, X[8192,512], W[64,512].  grid = (64, 3): CTA = 128 rows x 64
// cols, 256 threads = 8 warps (warp = m16 x n64).  k staged 64 at a time.
// ---------------------------------------------------------------------------
__global__ __launch_bounds__(256, 4) void qkv_proj_tc_kernel(
    const float* __restrict__ x,
    const float* __restrict__ Wq,
    const float* __restrict__ Wk,
    const float* __restrict__ Wv)
{
    extern __shared__ uint32_t psm[];
    uint32_t* Xs = psm;              // [128][SMS]
    uint32_t* Ws = psm + 128 * SMS;  // [64][SMS]

    const float* W;
    float* C;
    if (blockIdx.y == 0)      { W = Wq; C = g_Q; }
    else if (blockIdx.y == 1) { W = Wk; C = g_K; }
    else                      { W = Wv; C = g_V; }

    const int rbase = blockIdx.x * 128;
    const int tid  = threadIdx.x;
    const int wid  = tid >> 5;
    const int lane = tid & 31;
    const int g    = lane >> 2;
    const int qd   = lane & 3;
    const int mr   = wid * 16;

    float acc[8][4] = {};

    for (int k0 = 0; k0 < D_IN; k0 += 64) {
        __syncthreads();
        // stage X chunk [128][64] and W chunk [64][64] as tf32
        for (int i = tid; i < 128 * 16; i += 256) {
            int row = i >> 4, c4 = (i & 15) << 2;
            float4 v = *(const float4*)&x[(rbase + row) * D_IN + k0 + c4];
            uint4 b = make_uint4(f2tf32(v.x), f2tf32(v.y), f2tf32(v.z), f2tf32(v.w));
            *(uint4*)&Xs[row * SMS + c4] = b;
        }
        for (int i = tid; i < 64 * 16; i += 256) {
            int row = i >> 4, c4 = (i & 15) << 2;
            float4 v = *(const float4*)&W[row * D_IN + k0 + c4];
            uint4 b = make_uint4(f2tf32(v.x), f2tf32(v.y), f2tf32(v.z), f2tf32(v.w));
            *(uint4*)&Ws[row * SMS + c4] = b;
        }
        __syncthreads();

        #pragma unroll
        for (int kt = 0; kt < 8; kt++) {
            uint32_t a0 = Xs[(mr + g) * SMS + kt * 8 + qd];
            uint32_t a1 = Xs[(mr + g + 8) * SMS + kt * 8 + qd];
            uint32_t a2 = Xs[(mr + g) * SMS + kt * 8 + qd + 4];
            uint32_t a3 = Xs[(mr + g + 8) * SMS + kt * 8 + qd + 4];
            #pragma unroll
            for (int nt = 0; nt < 8; nt++) {
                uint32_t b0 = Ws[(nt * 8 + g) * SMS + kt * 8 + qd];
                uint32_t b1 = Ws[(nt * 8 + g) * SMS + kt * 8 + qd + 4];
                mma_tf32(acc[nt][0], acc[nt][1], acc[nt][2], acc[nt][3],
                         a0, a1, a2, a3, b0, b1);
            }
        }
    }

    #pragma unroll
    for (int nt = 0; nt < 8; nt++) {
        float* o0 = &C[(rbase + mr + g) * D_OUT + nt * 8 + 2 * qd];
        float* o1 = &C[(rbase + mr + g + 8) * D_OUT + nt * 8 + 2 * qd];
        *(float2*)o0 = make_float2(acc[nt][0], acc[nt][1]);
        *(float2*)o1 = make_float2(acc[nt][2], acc[nt][3]);
    }
}

// ---------------------------------------------------------------------------
// Kernel 2: split-K causal flash attention chunk (tf32 tensor cores).
// blockIdx.y = qblock, blockIdx.x = chunk of <=16 key tiles.
// smem: Ks[64][SMS] (aliased by Ps after QK), Vt[64][SMS] (V transposed:
// Vt[d][key] so PV B-frag reads hit the conflict-free 4g+qd pattern).
// 35 KB smem -> 6 CTAs/SM.
// ---------------------------------------------------------------------------
__global__ __launch_bounds__(128, 6) void attn_chunk_kernel()
{
    const int mblk  = blockIdx.y;
    const int chunk = blockIdx.x;
    const int n0 = chunk * CHUNK_TILES;
    if (n0 > mblk) return;
    const int n1 = min(n0 + CHUNK_TILES - 1, mblk);

    extern __shared__ uint32_t sm_u[];
    uint32_t* Ks = sm_u;                // [64][SMS]; reused as Ps after QK
    uint32_t* Vt = sm_u + 64 * SMS;     // [64][SMS] = V transposed [d][key]
    uint32_t* Ps = Ks;

    const int qbase = mblk * 64;
    const int tid   = threadIdx.x;
    const int wid   = tid >> 5;
    const int lane  = tid & 31;
    const int g     = lane >> 2;
    const int qd    = lane & 3;
    const int mr    = wid * 16;

    const float SC = 0.125f * 1.4426950408889634f; // (1/sqrt(64))*log2(e)

    // Q fragments, register-resident: qa[kt][0..3]
    uint32_t qa[8][4];
    #pragma unroll
    for (int kt = 0; kt < 8; kt++) {
        const float* q0 = &g_Q[(qbase + mr + g) * D_OUT + kt * 8 + qd];
        const float* q1 = &g_Q[(qbase + mr + g + 8) * D_OUT + kt * 8 + qd];
        qa[kt][0] = f2tf32(q0[0]);
        qa[kt][1] = f2tf32(q1[0]);
        qa[kt][2] = f2tf32(q0[4]);
        qa[kt][3] = f2tf32(q1[4]);
    }

    float O[8][4] = {};
    float m0 = -CUDART_INF_F, m1 = -CUDART_INF_F;
    float l0 = 0.f, l1 = 0.f;

    for (int nblk = n0; nblk <= n1; nblk++) {
        const int kbase = nblk * 64;
        __syncthreads();   // prev iter's PV reads (Ps/Vt) done before restage

        // Stage K row-major [key][d]; V transposed [d][key]. STS.128.
        for (int i = tid; i < 64 * 16; i += 128) {
            int row = i >> 4, c4 = (i & 15) << 2;
            float4 kv = *(const float4*)&g_K[(kbase + row) * D_OUT + c4];
            uint4 kb = make_uint4(f2tf32(kv.x), f2tf32(kv.y), f2tf32(kv.z), f2tf32(kv.w));
            *(uint4*)&Ks[row * SMS + c4] = kb;

            int d = i & 63, r4 = (i >> 6) << 2;
            uint4 vb;
            vb.x = f2tf32(g_V[(kbase + r4 + 0) * D_OUT + d]);
            vb.y = f2tf32(g_V[(kbase + r4 + 1) * D_OUT + d]);
            vb.z = f2tf32(g_V[(kbase + r4 + 2) * D_OUT + d]);
            vb.w = f2tf32(g_V[(kbase + r4 + 3) * D_OUT + d]);
            *(uint4*)&Vt[d * SMS + r4] = vb;
        }
        __syncthreads();

        // ----- scores S = Q K^T -----
        float s[8][4] = {};
        #pragma unroll
        for (int nt = 0; nt < 8; nt++) {
            #pragma unroll
            for (int kt = 0; kt < 8; kt++) {
                uint32_t b0 = Ks[(nt * 8 + g) * SMS + kt * 8 + qd];
                uint32_t b1 = Ks[(nt * 8 + g) * SMS + kt * 8 + qd + 4];
                mma_tf32(s[nt][0], s[nt][1], s[nt][2], s[nt][3],
                         qa[kt][0], qa[kt][1], qa[kt][2], qa[kt][3], b0, b1);
            }
        }
        __syncthreads();   // all K reads done; Ks may now be overwritten as Ps

        // causal mask on diagonal tile
        if (nblk == mblk) {
            const int r0 = mr + g, r1 = mr + g + 8;
            #pragma unroll
            for (int nt = 0; nt < 8; nt++) {
                int c = nt * 8 + 2 * qd;
                if (c     > r0) s[nt][0] = -CUDART_INF_F;
                if (c + 1 > r0) s[nt][1] = -CUDART_INF_F;
                if (c     > r1) s[nt][2] = -CUDART_INF_F;
                if (c + 1 > r1) s[nt][3] = -CUDART_INF_F;
            }
        }

        // ----- online softmax -----
        float rm0 = -CUDART_INF_F, rm1 = -CUDART_INF_F;
        #pragma unroll
        for (int nt = 0; nt < 8; nt++) {
            rm0 = fmaxf(rm0, fmaxf(s[nt][0], s[nt][1]));
            rm1 = fmaxf(rm1, fmaxf(s[nt][2], s[nt][3]));
        }
        rm0 = fmaxf(rm0, __shfl_xor_sync(0xffffffffu, rm0, 1));
        rm0 = fmaxf(rm0, __shfl_xor_sync(0xffffffffu, rm0, 2));
        rm1 = fmaxf(rm1, __shfl_xor_sync(0xffffffffu, rm1, 1));
        rm1 = fmaxf(rm1, __shfl_xor_sync(0xffffffffu, rm1, 2));

        float mn0 = fmaxf(m0, rm0);
        float mn1 = fmaxf(m1, rm1);
        float al0 = fast_ex2((m0 - mn0) * SC);
        float al1 = fast_ex2((m1 - mn1) * SC);
        m0 = mn0; m1 = mn1;

        float rs0 = 0.f, rs1 = 0.f;
        #pragma unroll
        for (int nt = 0; nt < 8; nt++) {
            float p00 = fast_ex2((s[nt][0] - mn0) * SC);
            float p01 = fast_ex2((s[nt][1] - mn0) * SC);
            float p10 = fast_ex2((s[nt][2] - mn1) * SC);
            float p11 = fast_ex2((s[nt][3] - mn1) * SC);
            rs0 += p00 + p01;
            rs1 += p10 + p11;
            uint32_t* p0 = &Ps[(mr + g) * SMS + nt * 8 + 2 * qd];
            uint32_t* p1 = &Ps[(mr + g + 8) * SMS + nt * 8 + 2 * qd];
            *(uint2*)p0 = make_uint2(f2tf32(p00), f2tf32(p01));
            *(uint2*)p1 = make_uint2(f2tf32(p10), f2tf32(p11));
        }
        rs0 += __shfl_xor_sync(0xffffffffu, rs0, 1);
        rs0 += __shfl_xor_sync(0xffffffffu, rs0, 2);
        rs1 += __shfl_xor_sync(0xffffffffu, rs1, 1);
        rs1 += __shfl_xor_sync(0xffffffffu, rs1, 2);
        l0 = l0 * al0 + rs0;
        l1 = l1 * al1 + rs1;

        #pragma unroll
        for (int nt = 0; nt < 8; nt++) {
            O[nt][0] *= al0; O[nt][1] *= al0;
            O[nt][2] *= al1; O[nt][3] *= al1;
        }
        __syncwarp();   // P stores visible within warp (A-frags are warp-local)

        // ----- O += P V  (B-frags from Vt: conflict-free pattern) -----
        #pragma unroll
        for (int kt = 0; kt < 8; kt++) {
            uint32_t pa0 = Ps[(mr + g) * SMS + kt * 8 + qd];
            uint32_t pa1 = Ps[(mr + g + 8) * SMS + kt * 8 + qd];
            uint32_t pa2 = Ps[(mr + g) * SMS + kt * 8 + qd + 4];
            uint32_t pa3 = Ps[(mr + g + 8) * SMS + kt * 8 + qd + 4];
            #pragma unroll
            for (int nt = 0; nt < 8; nt++) {
                uint32_t b0 = Vt[(nt * 8 + g) * SMS + kt * 8 + qd];
                uint32_t b1 = Vt[(nt * 8 + g) * SMS + kt * 8 + qd + 4];
                mma_tf32(O[nt][0], O[nt][1], O[nt][2], O[nt][3],
                         pa0, pa1, pa2, pa3, b0, b1);
            }
        }
    }

    // ----- write partials -----
    const int pbase = (mblk * MAX_CHUNKS + chunk) * 64;
    const int r0 = mr + g, r1 = mr + g + 8;
    #pragma unroll
    for (int nt = 0; nt < 8; nt++) {
        float* o0 = &g_Op[(pbase + r0) * 64 + nt * 8 + 2 * qd];
        float* o1 = &g_Op[(pbase + r1) * 64 + nt * 8 + 2 * qd];
        *(float2*)o0 = make_float2(O[nt][0], O[nt][1]);
        *(float2*)o1 = make_float2(O[nt][2], O[nt][3]);
    }
    if (qd == 0) {
        g_m[pbase + r0] = m0;  g_m[pbase + r1] = m1;
        g_l[pbase + r0] = l0;  g_l[pbase + r1] = l1;
    }
}

// ---------------------------------------------------------------------------
// Kernel 3: combine split-K partials.  grid = 128 qblocks, 128 threads.
// ---------------------------------------------------------------------------
__global__ __launch_bounds__(128) void attn_reduce_kernel(float* __restrict__ out)
{
    const int qblk = blockIdx.x;
    const int nch  = qblk / CHUNK_TILES + 1;
    const int tid  = threadIdx.x;
    const int r    = tid >> 1;
    const int c0   = (tid & 1) * 32;
    const float SC = 0.125f * 1.4426950408889634f;

    const int pbase = qblk * MAX_CHUNKS * 64;

    float mv[MAX_CHUNKS];
    float M = -CUDART_INF_F;
    for (int i = 0; i < nch; i++) {
        mv[i] = g_m[pbase + i * 64 + r];
        M = fmaxf(M, mv[i]);
    }

    float acc[32];
    #pragma unroll
    for (int j = 0; j < 32; j++) acc[j] = 0.f;
    float wl = 0.f;

    for (int i = 0; i < nch; i++) {
        float w = fast_ex2((mv[i] - M) * SC);
        wl += w * g_l[pbase + i * 64 + r];
        const float* Op = &g_Op[(pbase + i * 64 + r) * 64 + c0];
        #pragma unroll
        for (int j4 = 0; j4 < 8; j4++) {
            float4 v = *(const float4*)&Op[j4 * 4];
            acc[j4 * 4 + 0] += w * v.x;
            acc[j4 * 4 + 1] += w * v.y;
            acc[j4 * 4 + 2] += w * v.z;
            acc[j4 * 4 + 3] += w * v.w;
        }
    }

    const float inv = 1.0f / wl;
    float* o = &out[(qblk * 64 + r) * D_OUT + c0];
    #pragma unroll
    for (int j4 = 0; j4 < 8; j4++) {
        *(float4*)&o[j4 * 4] = make_float4(acc[j4 * 4 + 0] * inv,
                                           acc[j4 * 4 + 1] * inv,
                                           acc[j4 * 4 + 2] * inv,
                                           acc[j4 * 4 + 3] * inv);
    }
}

// ---------------------------------------------------------------------------
extern "C" void kernel_launch(void* const* d_in, const int* in_sizes, int n_in,
                              void* d_out, int out_size)
{
    const float* x  = (const float*)d_in[0];
    const float* Wq = (const float*)d_in[1];
    const float* Wk = (const float*)d_in[2];
    const float* Wv = (const float*)d_in[3];
    float* out = (float*)d_out;

    const int proj_smem = (128 + 64) * SMS * 4;  // 52224 bytes
    const int attn_smem = 2 * 64 * SMS * 4;      // 34816 bytes
    cudaFuncSetAttribute(qkv_proj_tc_kernel,
                         cudaFuncAttributeMaxDynamicSharedMemorySize, proj_smem);
    cudaFuncSetAttribute(attn_chunk_kernel,
                         cudaFuncAttributeMaxDynamicSharedMemorySize, attn_smem);

    dim3 g1(S_LEN / 128, 3);
    qkv_proj_tc_kernel<<<g1, 256, proj_smem>>>(x, Wq, Wk, Wv);
    dim3 g2(MAX_CHUNKS, S_LEN / 64);
    attn_chunk_kernel<<<g2, 128, attn_smem>>>();
    attn_reduce_kernel<<<S_LEN / 64, 128>>>(out);
}

// round 5
// speedup vs baseline: 1.5974x; 1.5974x over previous
#include <cuda_runtime.h>
#include <math_constants.h>
#include <cstdint>

#define S_LEN 8192
#define D_IN  512
#define D_OUT 64

#define CHUNK_TILES 16          // key tiles (of 64) per chunk CTA
#define MAX_CHUNKS  8           // ceil(128 / 16)
#define SMS 68                  // smem row stride (words)

// Scratch (device globals: no allocation in kernel_launch)
__device__ float g_Q[S_LEN * D_OUT];
__device__ float g_K[S_LEN * D_OUT];
__device__ float g_V[S_LEN * D_OUT];
// split-K partials: per (qblk, chunk): unnormalized O[64][64], m[64], l[64]
__device__ float g_Op[128 * MAX_CHUNKS * 64 * 64];
__device__ float g_m [128 * MAX_CHUNKS * 64];
__device__ float g_l [128 * MAX_CHUNKS * 64];

// ---------------------------------------------------------------------------
// tf32 mma.sync helpers
// ---------------------------------------------------------------------------
__device__ __forceinline__ uint32_t f2tf32(float x) {
    uint32_t r;
    asm("cvt.rna.tf32.f32 %0, %1;" : "=r"(r) : "f"(x));
    return r;
}

__device__ __forceinline__ float fast_ex2(float x) {
    float y;
    asm("ex2.approx.ftz.f32 %0, %1;" : "=f"(y) : "f"(x));
    return y;
}

__device__ __forceinline__ void mma_tf32(
    float& d0, float& d1, float& d2, float& d3,
    uint32_t a0, uint32_t a1, uint32_t a2, uint32_t a3,
    uint32_t b0, uint32_t b1)
{
    asm volatile(
        "mma.sync.aligned.m16n8k8.row.col.f32.tf32.tf32.f32 "
        "{%0,%1,%2,%3}, {%4,%5,%6,%7}, {%8,%9}, {%0,%1,%2,%3};\n"
        : "+f"(d0), "+f"(d1), "+f"(d2), "+f"(d3)
        : "r"(a0), "r"(a1), "r"(a2), "r"(a3), "r"(b0), "r"(b1));
}

// ---------------------------------------------------------------------------
// Kernel 1: QKV projection via tf32 tensor cores, register-prefetch pipelined.
// C = X @ W^T, X[8192,512], W[64,512].  grid = (64, 3): CTA = 128 rows x 64
// cols, 256 threads = 8 warps (warp = m16 x n64).  k staged 64 at a time;
// chunk c+1 is LDG'd into registers while chunk c's mmas run.
// ---------------------------------------------------------------------------
__global__ __launch_bounds__(256, 2) void qkv_proj_tc_kernel(
    const float* __restrict__ x,
    const float* __restrict__ Wq,
    const float* __restrict__ Wk,
    const float* __restrict__ Wv)
{
    extern __shared__ uint32_t psm[];
    uint32_t* Xs = psm;              // [128][SMS]
    uint32_t* Ws = psm + 128 * SMS;  // [64][SMS]

    const float* W;
    float* C;
    if (blockIdx.y == 0)      { W = Wq; C = g_Q; }
    else if (blockIdx.y == 1) { W = Wk; C = g_K; }
    else                      { W = Wv; C = g_V; }

    const int rbase = blockIdx.x * 128;
    const int tid  = threadIdx.x;
    const int wid  = tid >> 5;
    const int lane = tid & 31;
    const int g    = lane >> 2;
    const int qd   = lane & 3;
    const int mr   = wid * 16;

    // staging coordinates: thread covers rows r0+16j, fixed 4-col group c4
    const int r0 = tid >> 4;
    const int c4 = (tid & 15) << 2;

    float4 xreg[8];   // X chunk prefetch: rows r0+16j (j<8)
    float4 wreg[4];   // W chunk prefetch: rows r0+16j (j<4)

    // prefetch chunk 0
    #pragma unroll
    for (int j = 0; j < 8; j++)
        xreg[j] = *(const float4*)&x[(rbase + r0 + 16 * j) * D_IN + c4];
    #pragma unroll
    for (int j = 0; j < 4; j++)
        wreg[j] = *(const float4*)&W[(r0 + 16 * j) * D_IN + c4];

    float acc[8][4] = {};

    for (int c = 0; c < D_IN / 64; c++) {
        // stage prefetched regs (cvt to tf32)
        #pragma unroll
        for (int j = 0; j < 8; j++) {
            float4 v = xreg[j];
            *(uint4*)&Xs[(r0 + 16 * j) * SMS + c4] =
                make_uint4(f2tf32(v.x), f2tf32(v.y), f2tf32(v.z), f2tf32(v.w));
        }
        #pragma unroll
        for (int j = 0; j < 4; j++) {
            float4 v = wreg[j];
            *(uint4*)&Ws[(r0 + 16 * j) * SMS + c4] =
                make_uint4(f2tf32(v.x), f2tf32(v.y), f2tf32(v.z), f2tf32(v.w));
        }
        __syncthreads();

        // prefetch next chunk (latency overlapped by the mmas below)
        if (c < D_IN / 64 - 1) {
            const int k0 = (c + 1) * 64;
            #pragma unroll
            for (int j = 0; j < 8; j++)
                xreg[j] = *(const float4*)&x[(rbase + r0 + 16 * j) * D_IN + k0 + c4];
            #pragma unroll
            for (int j = 0; j < 4; j++)
                wreg[j] = *(const float4*)&W[(r0 + 16 * j) * D_IN + k0 + c4];
        }

        #pragma unroll
        for (int kt = 0; kt < 8; kt++) {
            uint32_t a0 = Xs[(mr + g) * SMS + kt * 8 + qd];
            uint32_t a1 = Xs[(mr + g + 8) * SMS + kt * 8 + qd];
            uint32_t a2 = Xs[(mr + g) * SMS + kt * 8 + qd + 4];
            uint32_t a3 = Xs[(mr + g + 8) * SMS + kt * 8 + qd + 4];
            #pragma unroll
            for (int nt = 0; nt < 8; nt++) {
                uint32_t b0 = Ws[(nt * 8 + g) * SMS + kt * 8 + qd];
                uint32_t b1 = Ws[(nt * 8 + g) * SMS + kt * 8 + qd + 4];
                mma_tf32(acc[nt][0], acc[nt][1], acc[nt][2], acc[nt][3],
                         a0, a1, a2, a3, b0, b1);
            }
        }
        __syncthreads();
    }

    #pragma unroll
    for (int nt = 0; nt < 8; nt++) {
        float* o0 = &C[(rbase + mr + g) * D_OUT + nt * 8 + 2 * qd];
        float* o1 = &C[(rbase + mr + g + 8) * D_OUT + nt * 8 + 2 * qd];
        *(float2*)o0 = make_float2(acc[nt][0], acc[nt][1]);
        *(float2*)o1 = make_float2(acc[nt][2], acc[nt][3]);
    }
}

// ---------------------------------------------------------------------------
// Kernel 2: split-K causal flash attention chunk (tf32 tensor cores).
// R3 structure (separate Ps, natural register budget), with V staged
// transposed (Vt[d][key]) so PV B-frag reads are bank-conflict-free.
// ---------------------------------------------------------------------------
__global__ __launch_bounds__(128) void attn_chunk_kernel()
{
    const int mblk  = blockIdx.y;
    const int chunk = blockIdx.x;
    const int n0 = chunk * CHUNK_TILES;
    if (n0 > mblk) return;
    const int n1 = min(n0 + CHUNK_TILES - 1, mblk);

    extern __shared__ uint32_t sm_u[];
    uint32_t* Ks = sm_u;                // [64][SMS]
    uint32_t* Vt = sm_u + 64 * SMS;     // [64][SMS] = V transposed [d][key]
    uint32_t* Ps = sm_u + 2 * 64 * SMS; // [64][SMS]

    const int qbase = mblk * 64;
    const int tid   = threadIdx.x;
    const int wid   = tid >> 5;
    const int lane  = tid & 31;
    const int g     = lane >> 2;
    const int qd    = lane & 3;
    const int mr    = wid * 16;

    const float SC = 0.125f * 1.4426950408889634f; // (1/sqrt(64))*log2(e)

    // Q fragments, register-resident
    uint32_t qa[8][4];
    #pragma unroll
    for (int kt = 0; kt < 8; kt++) {
        const float* q0 = &g_Q[(qbase + mr + g) * D_OUT + kt * 8 + qd];
        const float* q1 = &g_Q[(qbase + mr + g + 8) * D_OUT + kt * 8 + qd];
        qa[kt][0] = f2tf32(q0[0]);
        qa[kt][1] = f2tf32(q1[0]);
        qa[kt][2] = f2tf32(q0[4]);
        qa[kt][3] = f2tf32(q1[4]);
    }

    float O[8][4] = {};
    float m0 = -CUDART_INF_F, m1 = -CUDART_INF_F;
    float l0 = 0.f, l1 = 0.f;

    for (int nblk = n0; nblk <= n1; nblk++) {
        const int kbase = nblk * 64;
        __syncthreads();   // prev iter's Ks/Vt reads done before restage

        // Stage K row-major [key][d]; V transposed [d][key].
        for (int i = tid; i < 64 * 16; i += 128) {
            int row = i >> 4, cc = (i & 15) << 2;
            float4 kv = *(const float4*)&g_K[(kbase + row) * D_OUT + cc];
            *(uint4*)&Ks[row * SMS + cc] =
                make_uint4(f2tf32(kv.x), f2tf32(kv.y), f2tf32(kv.z), f2tf32(kv.w));

            int d = i & 63, r4 = (i >> 6) << 2;
            uint4 vb;
            vb.x = f2tf32(g_V[(kbase + r4 + 0) * D_OUT + d]);
            vb.y = f2tf32(g_V[(kbase + r4 + 1) * D_OUT + d]);
            vb.z = f2tf32(g_V[(kbase + r4 + 2) * D_OUT + d]);
            vb.w = f2tf32(g_V[(kbase + r4 + 3) * D_OUT + d]);
            *(uint4*)&Vt[d * SMS + r4] = vb;
        }
        __syncthreads();

        // ----- scores S = Q K^T -----
        float s[8][4] = {};
        #pragma unroll
        for (int nt = 0; nt < 8; nt++) {
            #pragma unroll
            for (int kt = 0; kt < 8; kt++) {
                uint32_t b0 = Ks[(nt * 8 + g) * SMS + kt * 8 + qd];
                uint32_t b1 = Ks[(nt * 8 + g) * SMS + kt * 8 + qd + 4];
                mma_tf32(s[nt][0], s[nt][1], s[nt][2], s[nt][3],
                         qa[kt][0], qa[kt][1], qa[kt][2], qa[kt][3], b0, b1);
            }
        }

        // causal mask on diagonal tile
        if (nblk == mblk) {
            const int r0 = mr + g, r1 = mr + g + 8;
            #pragma unroll
            for (int nt = 0; nt < 8; nt++) {
                int c = nt * 8 + 2 * qd;
                if (c     > r0) s[nt][0] = -CUDART_INF_F;
                if (c + 1 > r0) s[nt][1] = -CUDART_INF_F;
                if (c     > r1) s[nt][2] = -CUDART_INF_F;
                if (c + 1 > r1) s[nt][3] = -CUDART_INF_F;
            }
        }

        // ----- online softmax -----
        float rm0 = -CUDART_INF_F, rm1 = -CUDART_INF_F;
        #pragma unroll
        for (int nt = 0; nt < 8; nt++) {
            rm0 = fmaxf(rm0, fmaxf(s[nt][0], s[nt][1]));
            rm1 = fmaxf(rm1, fmaxf(s[nt][2], s[nt][3]));
        }
        rm0 = fmaxf(rm0, __shfl_xor_sync(0xffffffffu, rm0, 1));
        rm0 = fmaxf(rm0, __shfl_xor_sync(0xffffffffu, rm0, 2));
        rm1 = fmaxf(rm1, __shfl_xor_sync(0xffffffffu, rm1, 1));
        rm1 = fmaxf(rm1, __shfl_xor_sync(0xffffffffu, rm1, 2));

        float mn0 = fmaxf(m0, rm0);
        float mn1 = fmaxf(m1, rm1);
        float al0 = fast_ex2((m0 - mn0) * SC);
        float al1 = fast_ex2((m1 - mn1) * SC);
        m0 = mn0; m1 = mn1;

        float rs0 = 0.f, rs1 = 0.f;
        #pragma unroll
        for (int nt = 0; nt < 8; nt++) {
            float p00 = fast_ex2((s[nt][0] - mn0) * SC);
            float p01 = fast_ex2((s[nt][1] - mn0) * SC);
            float p10 = fast_ex2((s[nt][2] - mn1) * SC);
            float p11 = fast_ex2((s[nt][3] - mn1) * SC);
            rs0 += p00 + p01;
            rs1 += p10 + p11;
            uint32_t* p0 = &Ps[(mr + g) * SMS + nt * 8 + 2 * qd];
            uint32_t* p1 = &Ps[(mr + g + 8) * SMS + nt * 8 + 2 * qd];
            *(uint2*)p0 = make_uint2(f2tf32(p00), f2tf32(p01));
            *(uint2*)p1 = make_uint2(f2tf32(p10), f2tf32(p11));
        }
        rs0 += __shfl_xor_sync(0xffffffffu, rs0, 1);
        rs0 += __shfl_xor_sync(0xffffffffu, rs0, 2);
        rs1 += __shfl_xor_sync(0xffffffffu, rs1, 1);
        rs1 += __shfl_xor_sync(0xffffffffu, rs1, 2);
        l0 = l0 * al0 + rs0;
        l1 = l1 * al1 + rs1;

        #pragma unroll
        for (int nt = 0; nt < 8; nt++) {
            O[nt][0] *= al0; O[nt][1] *= al0;
            O[nt][2] *= al1; O[nt][3] *= al1;
        }
        __syncwarp();   // P stores visible within warp (A-frag rows warp-local)

        // ----- O += P V  (B-frags from Vt: conflict-free) -----
        #pragma unroll
        for (int kt = 0; kt < 8; kt++) {
            uint32_t pa0 = Ps[(mr + g) * SMS + kt * 8 + qd];
            uint32_t pa1 = Ps[(mr + g + 8) * SMS + kt * 8 + qd];
            uint32_t pa2 = Ps[(mr + g) * SMS + kt * 8 + qd + 4];
            uint32_t pa3 = Ps[(mr + g + 8) * SMS + kt * 8 + qd + 4];
            #pragma unroll
            for (int nt = 0; nt < 8; nt++) {
                uint32_t b0 = Vt[(nt * 8 + g) * SMS + kt * 8 + qd];
                uint32_t b1 = Vt[(nt * 8 + g) * SMS + kt * 8 + qd + 4];
                mma_tf32(O[nt][0], O[nt][1], O[nt][2], O[nt][3],
                         pa0, pa1, pa2, pa3, b0, b1);
            }
        }
    }

    // ----- write partials -----
    const int pbase = (mblk * MAX_CHUNKS + chunk) * 64;
    const int r0 = mr + g, r1 = mr + g + 8;
    #pragma unroll
    for (int nt = 0; nt < 8; nt++) {
        float* o0 = &g_Op[(pbase + r0) * 64 + nt * 8 + 2 * qd];
        float* o1 = &g_Op[(pbase + r1) * 64 + nt * 8 + 2 * qd];
        *(float2*)o0 = make_float2(O[nt][0], O[nt][1]);
        *(float2*)o1 = make_float2(O[nt][2], O[nt][3]);
    }
    if (qd == 0) {
        g_m[pbase + r0] = m0;  g_m[pbase + r1] = m1;
        g_l[pbase + r0] = l0;  g_l[pbase + r1] = l1;
    }
}

// ---------------------------------------------------------------------------
// Kernel 3: combine split-K partials.  grid = 128 qblocks, 128 threads.
// ---------------------------------------------------------------------------
__global__ __launch_bounds__(128) void attn_reduce_kernel(float* __restrict__ out)
{
    const int qblk = blockIdx.x;
    const int nch  = qblk / CHUNK_TILES + 1;
    const int tid  = threadIdx.x;
    const int r    = tid >> 1;
    const int c0   = (tid & 1) * 32;
    const float SC = 0.125f * 1.4426950408889634f;

    const int pbase = qblk * MAX_CHUNKS * 64;

    float mv[MAX_CHUNKS];
    float M = -CUDART_INF_F;
    for (int i = 0; i < nch; i++) {
        mv[i] = g_m[pbase + i * 64 + r];
        M = fmaxf(M, mv[i]);
    }

    float acc[32];
    #pragma unroll
    for (int j = 0; j < 32; j++) acc[j] = 0.f;
    float wl = 0.f;

    for (int i = 0; i < nch; i++) {
        float w = fast_ex2((mv[i] - M) * SC);
        wl += w * g_l[pbase + i * 64 + r];
        const float* Op = &g_Op[(pbase + i * 64 + r) * 64 + c0];
        #pragma unroll
        for (int j4 = 0; j4 < 8; j4++) {
            float4 v = *(const float4*)&Op[j4 * 4];
            acc[j4 * 4 + 0] += w * v.x;
            acc[j4 * 4 + 1] += w * v.y;
            acc[j4 * 4 + 2] += w * v.z;
            acc[j4 * 4 + 3] += w * v.w;
        }
    }

    const float inv = 1.0f / wl;
    float* o = &out[(qblk * 64 + r) * D_OUT + c0];
    #pragma unroll
    for (int j4 = 0; j4 < 8; j4++) {
        *(float4*)&o[j4 * 4] = make_float4(acc[j4 * 4 + 0] * inv,
                                           acc[j4 * 4 + 1] * inv,
                                           acc[j4 * 4 + 2] * inv,
                                           acc[j4 * 4 + 3] * inv);
    }
}

// ---------------------------------------------------------------------------
extern "C" void kernel_launch(void* const* d_in, const int* in_sizes, int n_in,
                              void* d_out, int out_size)
{
    const float* x  = (const float*)d_in[0];
    const float* Wq = (const float*)d_in[1];
    const float* Wk = (const float*)d_in[2];
    const float* Wv = (const float*)d_in[3];
    float* out = (float*)d_out;

    const int proj_smem = (128 + 64) * SMS * 4;  // 52224 bytes
    const int attn_smem = 3 * 64 * SMS * 4;      // 52224 bytes
    cudaFuncSetAttribute(qkv_proj_tc_kernel,
                         cudaFuncAttributeMaxDynamicSharedMemorySize, proj_smem);
    cudaFuncSetAttribute(attn_chunk_kernel,
                         cudaFuncAttributeMaxDynamicSharedMemorySize, attn_smem);

    dim3 g1(S_LEN / 128, 3);
    qkv_proj_tc_kernel<<<g1, 256, proj_smem>>>(x, Wq, Wk, Wv);
    dim3 g2(MAX_CHUNKS, S_LEN / 64);
    attn_chunk_kernel<<<g2, 128, attn_smem>>>();
    attn_reduce_kernel<<<S_LEN / 64, 128>>>(out);
}

// round 6
// speedup vs baseline: 1.6842x; 1.0543x over previous
#include <cuda_runtime.h>
#include <math_constants.h>
#include <cstdint>

#define S_LEN 8192
#define D_IN  512
#define D_OUT 64

#define CHUNK_TILES 16          // key tiles (of 64) per chunk CTA
#define MAX_CHUNKS  8           // ceil(128 / 16)
#define SMS 68                  // smem row stride (words)

// Scratch (device globals: no allocation in kernel_launch)
__device__ float g_Q[S_LEN * D_OUT];
__device__ float g_K[S_LEN * D_OUT];
__device__ float g_V[S_LEN * D_OUT];
// split-K partials: per (qblk, chunk): unnormalized O[64][64], m[64], l[64]
__device__ float g_Op[128 * MAX_CHUNKS * 64 * 64];
__device__ float g_m [128 * MAX_CHUNKS * 64];
__device__ float g_l [128 * MAX_CHUNKS * 64];

// ---------------------------------------------------------------------------
// tf32 mma.sync helpers
// ---------------------------------------------------------------------------
__device__ __forceinline__ uint32_t f2tf32(float x) {
    uint32_t r;
    asm("cvt.rna.tf32.f32 %0, %1;" : "=r"(r) : "f"(x));
    return r;
}

__device__ __forceinline__ float fast_ex2(float x) {
    float y;
    asm("ex2.approx.ftz.f32 %0, %1;" : "=f"(y) : "f"(x));
    return y;
}

__device__ __forceinline__ void mma_tf32(
    float& d0, float& d1, float& d2, float& d3,
    uint32_t a0, uint32_t a1, uint32_t a2, uint32_t a3,
    uint32_t b0, uint32_t b1)
{
    asm volatile(
        "mma.sync.aligned.m16n8k8.row.col.f32.tf32.tf32.f32 "
        "{%0,%1,%2,%3}, {%4,%5,%6,%7}, {%8,%9}, {%0,%1,%2,%3};\n"
        : "+f"(d0), "+f"(d1), "+f"(d2), "+f"(d3)
        : "r"(a0), "r"(a1), "r"(a2), "r"(a3), "r"(b0), "r"(b1));
}

// ---------------------------------------------------------------------------
// Kernel 1: QKV projection via tf32 tensor cores, register-prefetch pipelined.
// (unchanged from R5: 26us measured)
// ---------------------------------------------------------------------------
__global__ __launch_bounds__(256, 2) void qkv_proj_tc_kernel(
    const float* __restrict__ x,
    const float* __restrict__ Wq,
    const float* __restrict__ Wk,
    const float* __restrict__ Wv)
{
    extern __shared__ uint32_t psm[];
    uint32_t* Xs = psm;              // [128][SMS]
    uint32_t* Ws = psm + 128 * SMS;  // [64][SMS]

    const float* W;
    float* C;
    if (blockIdx.y == 0)      { W = Wq; C = g_Q; }
    else if (blockIdx.y == 1) { W = Wk; C = g_K; }
    else                      { W = Wv; C = g_V; }

    const int rbase = blockIdx.x * 128;
    const int tid  = threadIdx.x;
    const int wid  = tid >> 5;
    const int lane = tid & 31;
    const int g    = lane >> 2;
    const int qd   = lane & 3;
    const int mr   = wid * 16;

    const int r0 = tid >> 4;
    const int c4 = (tid & 15) << 2;

    float4 xreg[8];
    float4 wreg[4];

    #pragma unroll
    for (int j = 0; j < 8; j++)
        xreg[j] = *(const float4*)&x[(rbase + r0 + 16 * j) * D_IN + c4];
    #pragma unroll
    for (int j = 0; j < 4; j++)
        wreg[j] = *(const float4*)&W[(r0 + 16 * j) * D_IN + c4];

    float acc[8][4] = {};

    for (int c = 0; c < D_IN / 64; c++) {
        #pragma unroll
        for (int j = 0; j < 8; j++) {
            float4 v = xreg[j];
            *(uint4*)&Xs[(r0 + 16 * j) * SMS + c4] =
                make_uint4(f2tf32(v.x), f2tf32(v.y), f2tf32(v.z), f2tf32(v.w));
        }
        #pragma unroll
        for (int j = 0; j < 4; j++) {
            float4 v = wreg[j];
            *(uint4*)&Ws[(r0 + 16 * j) * SMS + c4] =
                make_uint4(f2tf32(v.x), f2tf32(v.y), f2tf32(v.z), f2tf32(v.w));
        }
        __syncthreads();

        if (c < D_IN / 64 - 1) {
            const int k0 = (c + 1) * 64;
            #pragma unroll
            for (int j = 0; j < 8; j++)
                xreg[j] = *(const float4*)&x[(rbase + r0 + 16 * j) * D_IN + k0 + c4];
            #pragma unroll
            for (int j = 0; j < 4; j++)
                wreg[j] = *(const float4*)&W[(r0 + 16 * j) * D_IN + k0 + c4];
        }

        #pragma unroll
        for (int kt = 0; kt < 8; kt++) {
            uint32_t a0 = Xs[(mr + g) * SMS + kt * 8 + qd];
            uint32_t a1 = Xs[(mr + g + 8) * SMS + kt * 8 + qd];
            uint32_t a2 = Xs[(mr + g) * SMS + kt * 8 + qd + 4];
            uint32_t a3 = Xs[(mr + g + 8) * SMS + kt * 8 + qd + 4];
            #pragma unroll
            for (int nt = 0; nt < 8; nt++) {
                uint32_t b0 = Ws[(nt * 8 + g) * SMS + kt * 8 + qd];
                uint32_t b1 = Ws[(nt * 8 + g) * SMS + kt * 8 + qd + 4];
                mma_tf32(acc[nt][0], acc[nt][1], acc[nt][2], acc[nt][3],
                         a0, a1, a2, a3, b0, b1);
            }
        }
        __syncthreads();
    }

    #pragma unroll
    for (int nt = 0; nt < 8; nt++) {
        float* o0 = &C[(rbase + mr + g) * D_OUT + nt * 8 + 2 * qd];
        float* o1 = &C[(rbase + mr + g + 8) * D_OUT + nt * 8 + 2 * qd];
        *(float2*)o0 = make_float2(acc[nt][0], acc[nt][1]);
        *(float2*)o1 = make_float2(acc[nt][2], acc[nt][3]);
    }
}

// ---------------------------------------------------------------------------
// Kernel 2: split-K causal flash attention chunk (tf32 tensor cores).
// NEW in R6: next tile's K/V is prefetched into registers (cvt at load)
// while the current tile's mma/softmax runs — staging between the barriers
// is pure STS, removing the L2 latency from the per-tile critical path.
// ---------------------------------------------------------------------------
__global__ __launch_bounds__(128) void attn_chunk_kernel()
{
    const int mblk  = blockIdx.y;
    const int chunk = blockIdx.x;
    const int n0 = chunk * CHUNK_TILES;
    if (n0 > mblk) return;
    const int n1 = min(n0 + CHUNK_TILES - 1, mblk);

    extern __shared__ uint32_t sm_u[];
    uint32_t* Ks = sm_u;                // [64][SMS]
    uint32_t* Vt = sm_u + 64 * SMS;     // [64][SMS] = V transposed [d][key]
    uint32_t* Ps = sm_u + 2 * 64 * SMS; // [64][SMS]

    const int qbase = mblk * 64;
    const int tid   = threadIdx.x;
    const int wid   = tid >> 5;
    const int lane  = tid & 31;
    const int g     = lane >> 2;
    const int qd    = lane & 3;
    const int mr    = wid * 16;

    const float SC = 0.125f * 1.4426950408889634f; // (1/sqrt(64))*log2(e)

    // Q fragments, register-resident
    uint32_t qa[8][4];
    #pragma unroll
    for (int kt = 0; kt < 8; kt++) {
        const float* q0 = &g_Q[(qbase + mr + g) * D_OUT + kt * 8 + qd];
        const float* q1 = &g_Q[(qbase + mr + g + 8) * D_OUT + kt * 8 + qd];
        qa[kt][0] = f2tf32(q0[0]);
        qa[kt][1] = f2tf32(q1[0]);
        qa[kt][2] = f2tf32(q0[4]);
        qa[kt][3] = f2tf32(q1[4]);
    }

    // K/V register prefetch buffers (tf32 bits)
    uint4 kpre[8], vpre[8];

    auto prefetch = [&](int kbase) {
        #pragma unroll
        for (int j = 0; j < 8; j++) {
            const int i = tid + j * 128;
            const int row = i >> 4, cc = (i & 15) << 2;
            float4 kv = *(const float4*)&g_K[(kbase + row) * D_OUT + cc];
            kpre[j] = make_uint4(f2tf32(kv.x), f2tf32(kv.y),
                                 f2tf32(kv.z), f2tf32(kv.w));
            const int d = i & 63, r4 = (i >> 6) << 2;
            vpre[j].x = f2tf32(g_V[(kbase + r4 + 0) * D_OUT + d]);
            vpre[j].y = f2tf32(g_V[(kbase + r4 + 1) * D_OUT + d]);
            vpre[j].z = f2tf32(g_V[(kbase + r4 + 2) * D_OUT + d]);
            vpre[j].w = f2tf32(g_V[(kbase + r4 + 3) * D_OUT + d]);
        }
    };

    prefetch(n0 * 64);

    float O[8][4] = {};
    float m0 = -CUDART_INF_F, m1 = -CUDART_INF_F;
    float l0 = 0.f, l1 = 0.f;

    for (int nblk = n0; nblk <= n1; nblk++) {
        __syncthreads();   // prev iter's Ks/Vt reads done before restage

        // Stage prefetched K (row-major) and V (transposed) — pure STS.
        #pragma unroll
        for (int j = 0; j < 8; j++) {
            const int i = tid + j * 128;
            const int row = i >> 4, cc = (i & 15) << 2;
            *(uint4*)&Ks[row * SMS + cc] = kpre[j];
            const int d = i & 63, r4 = (i >> 6) << 2;
            *(uint4*)&Vt[d * SMS + r4] = vpre[j];
        }
        __syncthreads();

        // Prefetch next tile (latency overlapped by mma/softmax below)
        if (nblk < n1) prefetch((nblk + 1) * 64);

        // ----- scores S = Q K^T -----
        float s[8][4] = {};
        #pragma unroll
        for (int nt = 0; nt < 8; nt++) {
            #pragma unroll
            for (int kt = 0; kt < 8; kt++) {
                uint32_t b0 = Ks[(nt * 8 + g) * SMS + kt * 8 + qd];
                uint32_t b1 = Ks[(nt * 8 + g) * SMS + kt * 8 + qd + 4];
                mma_tf32(s[nt][0], s[nt][1], s[nt][2], s[nt][3],
                         qa[kt][0], qa[kt][1], qa[kt][2], qa[kt][3], b0, b1);
            }
        }

        // causal mask on diagonal tile
        if (nblk == mblk) {
            const int r0 = mr + g, r1 = mr + g + 8;
            #pragma unroll
            for (int nt = 0; nt < 8; nt++) {
                int c = nt * 8 + 2 * qd;
                if (c     > r0) s[nt][0] = -CUDART_INF_F;
                if (c + 1 > r0) s[nt][1] = -CUDART_INF_F;
                if (c     > r1) s[nt][2] = -CUDART_INF_F;
                if (c + 1 > r1) s[nt][3] = -CUDART_INF_F;
            }
        }

        // ----- online softmax -----
        float rm0 = -CUDART_INF_F, rm1 = -CUDART_INF_F;
        #pragma unroll
        for (int nt = 0; nt < 8; nt++) {
            rm0 = fmaxf(rm0, fmaxf(s[nt][0], s[nt][1]));
            rm1 = fmaxf(rm1, fmaxf(s[nt][2], s[nt][3]));
        }
        rm0 = fmaxf(rm0, __shfl_xor_sync(0xffffffffu, rm0, 1));
        rm0 = fmaxf(rm0, __shfl_xor_sync(0xffffffffu, rm0, 2));
        rm1 = fmaxf(rm1, __shfl_xor_sync(0xffffffffu, rm1, 1));
        rm1 = fmaxf(rm1, __shfl_xor_sync(0xffffffffu, rm1, 2));

        float mn0 = fmaxf(m0, rm0);
        float mn1 = fmaxf(m1, rm1);
        float al0 = fast_ex2((m0 - mn0) * SC);
        float al1 = fast_ex2((m1 - mn1) * SC);
        m0 = mn0; m1 = mn1;

        float rs0 = 0.f, rs1 = 0.f;
        #pragma unroll
        for (int nt = 0; nt < 8; nt++) {
            float p00 = fast_ex2((s[nt][0] - mn0) * SC);
            float p01 = fast_ex2((s[nt][1] - mn0) * SC);
            float p10 = fast_ex2((s[nt][2] - mn1) * SC);
            float p11 = fast_ex2((s[nt][3] - mn1) * SC);
            rs0 += p00 + p01;
            rs1 += p10 + p11;
            uint32_t* p0 = &Ps[(mr + g) * SMS + nt * 8 + 2 * qd];
            uint32_t* p1 = &Ps[(mr + g + 8) * SMS + nt * 8 + 2 * qd];
            *(uint2*)p0 = make_uint2(f2tf32(p00), f2tf32(p01));
            *(uint2*)p1 = make_uint2(f2tf32(p10), f2tf32(p11));
        }
        rs0 += __shfl_xor_sync(0xffffffffu, rs0, 1);
        rs0 += __shfl_xor_sync(0xffffffffu, rs0, 2);
        rs1 += __shfl_xor_sync(0xffffffffu, rs1, 1);
        rs1 += __shfl_xor_sync(0xffffffffu, rs1, 2);
        l0 = l0 * al0 + rs0;
        l1 = l1 * al1 + rs1;

        #pragma unroll
        for (int nt = 0; nt < 8; nt++) {
            O[nt][0] *= al0; O[nt][1] *= al0;
            O[nt][2] *= al1; O[nt][3] *= al1;
        }
        __syncwarp();   // P stores visible within warp (A-frag rows warp-local)

        // ----- O += P V  (B-frags from Vt: conflict-free) -----
        #pragma unroll
        for (int kt = 0; kt < 8; kt++) {
            uint32_t pa0 = Ps[(mr + g) * SMS + kt * 8 + qd];
            uint32_t pa1 = Ps[(mr + g + 8) * SMS + kt * 8 + qd];
            uint32_t pa2 = Ps[(mr + g) * SMS + kt * 8 + qd + 4];
            uint32_t pa3 = Ps[(mr + g + 8) * SMS + kt * 8 + qd + 4];
            #pragma unroll
            for (int nt = 0; nt < 8; nt++) {
                uint32_t b0 = Vt[(nt * 8 + g) * SMS + kt * 8 + qd];
                uint32_t b1 = Vt[(nt * 8 + g) * SMS + kt * 8 + qd + 4];
                mma_tf32(O[nt][0], O[nt][1], O[nt][2], O[nt][3],
                         pa0, pa1, pa2, pa3, b0, b1);
            }
        }
    }

    // ----- write partials -----
    const int pbase = (mblk * MAX_CHUNKS + chunk) * 64;
    const int r0 = mr + g, r1 = mr + g + 8;
    #pragma unroll
    for (int nt = 0; nt < 8; nt++) {
        float* o0 = &g_Op[(pbase + r0) * 64 + nt * 8 + 2 * qd];
        float* o1 = &g_Op[(pbase + r1) * 64 + nt * 8 + 2 * qd];
        *(float2*)o0 = make_float2(O[nt][0], O[nt][1]);
        *(float2*)o1 = make_float2(O[nt][2], O[nt][3]);
    }
    if (qd == 0) {
        g_m[pbase + r0] = m0;  g_m[pbase + r1] = m1;
        g_l[pbase + r0] = l0;  g_l[pbase + r1] = l1;
    }
}

// ---------------------------------------------------------------------------
// Kernel 3: combine split-K partials.  grid = 128 qblocks, 128 threads.
// ---------------------------------------------------------------------------
__global__ __launch_bounds__(128) void attn_reduce_kernel(float* __restrict__ out)
{
    const int qblk = blockIdx.x;
    const int nch  = qblk / CHUNK_TILES + 1;
    const int tid  = threadIdx.x;
    const int r    = tid >> 1;
    const int c0   = (tid & 1) * 32;
    const float SC = 0.125f * 1.4426950408889634f;

    const int pbase = qblk * MAX_CHUNKS * 64;

    float mv[MAX_CHUNKS];
    float M = -CUDART_INF_F;
    for (int i = 0; i < nch; i++) {
        mv[i] = g_m[pbase + i * 64 + r];
        M = fmaxf(M, mv[i]);
    }

    float acc[32];
    #pragma unroll
    for (int j = 0; j < 32; j++) acc[j] = 0.f;
    float wl = 0.f;

    for (int i = 0; i < nch; i++) {
        float w = fast_ex2((mv[i] - M) * SC);
        wl += w * g_l[pbase + i * 64 + r];
        const float* Op = &g_Op[(pbase + i * 64 + r) * 64 + c0];
        #pragma unroll
        for (int j4 = 0; j4 < 8; j4++) {
            float4 v = *(const float4*)&Op[j4 * 4];
            acc[j4 * 4 + 0] += w * v.x;
            acc[j4 * 4 + 1] += w * v.y;
            acc[j4 * 4 + 2] += w * v.z;
            acc[j4 * 4 + 3] += w * v.w;
        }
    }

    const float inv = 1.0f / wl;
    float* o = &out[(qblk * 64 + r) * D_OUT + c0];
    #pragma unroll
    for (int j4 = 0; j4 < 8; j4++) {
        *(float4*)&o[j4 * 4] = make_float4(acc[j4 * 4 + 0] * inv,
                                           acc[j4 * 4 + 1] * inv,
                                           acc[j4 * 4 + 2] * inv,
                                           acc[j4 * 4 + 3] * inv);
    }
}

// ---------------------------------------------------------------------------
extern "C" void kernel_launch(void* const* d_in, const int* in_sizes, int n_in,
                              void* d_out, int out_size)
{
    const float* x  = (const float*)d_in[0];
    const float* Wq = (const float*)d_in[1];
    const float* Wk = (const float*)d_in[2];
    const float* Wv = (const float*)d_in[3];
    float* out = (float*)d_out;

    const int proj_smem = (128 + 64) * SMS * 4;  // 52224 bytes
    const int attn_smem = 3 * 64 * SMS * 4;      // 52224 bytes
    cudaFuncSetAttribute(qkv_proj_tc_kernel,
                         cudaFuncAttributeMaxDynamicSharedMemorySize, proj_smem);
    cudaFuncSetAttribute(attn_chunk_kernel,
                         cudaFuncAttributeMaxDynamicSharedMemorySize, attn_smem);

    dim3 g1(S_LEN / 128, 3);
    qkv_proj_tc_kernel<<<g1, 256, proj_smem>>>(x, Wq, Wk, Wv);
    dim3 g2(MAX_CHUNKS, S_LEN / 64);
    attn_chunk_kernel<<<g2, 128, attn_smem>>>();
    attn_reduce_kernel<<<S_LEN / 64, 128>>>(out);
}

// round 7
// speedup vs baseline: 1.7461x; 1.0368x over previous
#include <cuda_runtime.h>
#include <math_constants.h>
#include <cstdint>

#define S_LEN 8192
#define D_IN  512
#define D_OUT 64

#define CHUNK_TILES 16          // key tiles (of 64) per chunk CTA
#define MAX_CHUNKS  8           // ceil(128 / 16)
#define SMS 68                  // smem row stride (words)

// Scratch (device globals: no allocation in kernel_launch)
__device__ float g_Q[S_LEN * D_OUT];
__device__ float g_K[S_LEN * D_OUT];
__device__ float g_V[S_LEN * D_OUT];
// split-K partials: per (qblk, chunk): unnormalized O[64][64], m[64], l[64]
__device__ float g_Op[128 * MAX_CHUNKS * 64 * 64];
__device__ float g_m [128 * MAX_CHUNKS * 64];
__device__ float g_l [128 * MAX_CHUNKS * 64];

// ---------------------------------------------------------------------------
// tf32 mma.sync helpers
// ---------------------------------------------------------------------------
__device__ __forceinline__ uint32_t f2tf32(float x) {
    uint32_t r;
    asm("cvt.rna.tf32.f32 %0, %1;" : "=r"(r) : "f"(x));
    return r;
}

__device__ __forceinline__ float fast_ex2(float x) {
    float y;
    asm("ex2.approx.ftz.f32 %0, %1;" : "=f"(y) : "f"(x));
    return y;
}

__device__ __forceinline__ void mma_tf32(
    float& d0, float& d1, float& d2, float& d3,
    uint32_t a0, uint32_t a1, uint32_t a2, uint32_t a3,
    uint32_t b0, uint32_t b1)
{
    asm volatile(
        "mma.sync.aligned.m16n8k8.row.col.f32.tf32.tf32.f32 "
        "{%0,%1,%2,%3}, {%4,%5,%6,%7}, {%8,%9}, {%0,%1,%2,%3};\n"
        : "+f"(d0), "+f"(d1), "+f"(d2), "+f"(d3)
        : "r"(a0), "r"(a1), "r"(a2), "r"(a3), "r"(b0), "r"(b1));
}

// ---------------------------------------------------------------------------
// Kernel 1: QKV projection via tf32 tensor cores, register-prefetch pipelined.
// (unchanged: 26us measured)
// ---------------------------------------------------------------------------
__global__ __launch_bounds__(256, 2) void qkv_proj_tc_kernel(
    const float* __restrict__ x,
    const float* __restrict__ Wq,
    const float* __restrict__ Wk,
    const float* __restrict__ Wv)
{
    extern __shared__ uint32_t psm[];
    uint32_t* Xs = psm;              // [128][SMS]
    uint32_t* Ws = psm + 128 * SMS;  // [64][SMS]

    const float* W;
    float* C;
    if (blockIdx.y == 0)      { W = Wq; C = g_Q; }
    else if (blockIdx.y == 1) { W = Wk; C = g_K; }
    else                      { W = Wv; C = g_V; }

    const int rbase = blockIdx.x * 128;
    const int tid  = threadIdx.x;
    const int wid  = tid >> 5;
    const int lane = tid & 31;
    const int g    = lane >> 2;
    const int qd   = lane & 3;
    const int mr   = wid * 16;

    const int r0 = tid >> 4;
    const int c4 = (tid & 15) << 2;

    float4 xreg[8];
    float4 wreg[4];

    #pragma unroll
    for (int j = 0; j < 8; j++)
        xreg[j] = *(const float4*)&x[(rbase + r0 + 16 * j) * D_IN + c4];
    #pragma unroll
    for (int j = 0; j < 4; j++)
        wreg[j] = *(const float4*)&W[(r0 + 16 * j) * D_IN + c4];

    float acc[8][4] = {};

    for (int c = 0; c < D_IN / 64; c++) {
        #pragma unroll
        for (int j = 0; j < 8; j++) {
            float4 v = xreg[j];
            *(uint4*)&Xs[(r0 + 16 * j) * SMS + c4] =
                make_uint4(f2tf32(v.x), f2tf32(v.y), f2tf32(v.z), f2tf32(v.w));
        }
        #pragma unroll
        for (int j = 0; j < 4; j++) {
            float4 v = wreg[j];
            *(uint4*)&Ws[(r0 + 16 * j) * SMS + c4] =
                make_uint4(f2tf32(v.x), f2tf32(v.y), f2tf32(v.z), f2tf32(v.w));
        }
        __syncthreads();

        if (c < D_IN / 64 - 1) {
            const int k0 = (c + 1) * 64;
            #pragma unroll
            for (int j = 0; j < 8; j++)
                xreg[j] = *(const float4*)&x[(rbase + r0 + 16 * j) * D_IN + k0 + c4];
            #pragma unroll
            for (int j = 0; j < 4; j++)
                wreg[j] = *(const float4*)&W[(r0 + 16 * j) * D_IN + k0 + c4];
        }

        #pragma unroll
        for (int kt = 0; kt < 8; kt++) {
            uint32_t a0 = Xs[(mr + g) * SMS + kt * 8 + qd];
            uint32_t a1 = Xs[(mr + g + 8) * SMS + kt * 8 + qd];
            uint32_t a2 = Xs[(mr + g) * SMS + kt * 8 + qd + 4];
            uint32_t a3 = Xs[(mr + g + 8) * SMS + kt * 8 + qd + 4];
            #pragma unroll
            for (int nt = 0; nt < 8; nt++) {
                uint32_t b0 = Ws[(nt * 8 + g) * SMS + kt * 8 + qd];
                uint32_t b1 = Ws[(nt * 8 + g) * SMS + kt * 8 + qd + 4];
                mma_tf32(acc[nt][0], acc[nt][1], acc[nt][2], acc[nt][3],
                         a0, a1, a2, a3, b0, b1);
            }
        }
        __syncthreads();
    }

    #pragma unroll
    for (int nt = 0; nt < 8; nt++) {
        float* o0 = &C[(rbase + mr + g) * D_OUT + nt * 8 + 2 * qd];
        float* o1 = &C[(rbase + mr + g + 8) * D_OUT + nt * 8 + 2 * qd];
        *(float2*)o0 = make_float2(acc[nt][0], acc[nt][1]);
        *(float2*)o1 = make_float2(acc[nt][2], acc[nt][3]);
    }
}

// ---------------------------------------------------------------------------
// Kernel 2: split-K causal flash attention chunk (tf32 tensor cores).
// R7: (a) ping-pong K/V smem buffers, ONE barrier per tile, STS overlapped
// with mma/softmax; (b) P delivered to PV via warp shuffles (C-frag -> A-frag
// permutation), removing the Ps smem buffer and its traffic.
// ---------------------------------------------------------------------------
__global__ __launch_bounds__(128) void attn_chunk_kernel()
{
    const int mblk  = blockIdx.y;
    const int chunk = blockIdx.x;
    const int n0 = chunk * CHUNK_TILES;
    if (n0 > mblk) return;
    const int n1 = min(n0 + CHUNK_TILES - 1, mblk);

    extern __shared__ uint32_t sm_u[];
    // buffer b: K at b*(2*64*SMS), Vt at b*(2*64*SMS) + 64*SMS

    const int qbase = mblk * 64;
    const int tid   = threadIdx.x;
    const int wid   = tid >> 5;
    const int lane  = tid & 31;
    const int g     = lane >> 2;
    const int qd    = lane & 3;
    const int mr    = wid * 16;

    const float SC = 0.125f * 1.4426950408889634f; // (1/sqrt(64))*log2(e)

    // Q fragments, register-resident
    uint32_t qa[8][4];
    #pragma unroll
    for (int kt = 0; kt < 8; kt++) {
        const float* q0 = &g_Q[(qbase + mr + g) * D_OUT + kt * 8 + qd];
        const float* q1 = &g_Q[(qbase + mr + g + 8) * D_OUT + kt * 8 + qd];
        qa[kt][0] = f2tf32(q0[0]);
        qa[kt][1] = f2tf32(q1[0]);
        qa[kt][2] = f2tf32(q0[4]);
        qa[kt][3] = f2tf32(q1[4]);
    }

    // K/V register prefetch buffers (tf32 bits)
    uint4 kpre[8], vpre[8];

    auto prefetch = [&](int kbase) {
        #pragma unroll
        for (int j = 0; j < 8; j++) {
            const int i = tid + j * 128;
            const int row = i >> 4, cc = (i & 15) << 2;
            float4 kv = *(const float4*)&g_K[(kbase + row) * D_OUT + cc];
            kpre[j] = make_uint4(f2tf32(kv.x), f2tf32(kv.y),
                                 f2tf32(kv.z), f2tf32(kv.w));
            const int d = i & 63, r4 = (i >> 6) << 2;
            vpre[j].x = f2tf32(g_V[(kbase + r4 + 0) * D_OUT + d]);
            vpre[j].y = f2tf32(g_V[(kbase + r4 + 1) * D_OUT + d]);
            vpre[j].z = f2tf32(g_V[(kbase + r4 + 2) * D_OUT + d]);
            vpre[j].w = f2tf32(g_V[(kbase + r4 + 3) * D_OUT + d]);
        }
    };

    auto stage = [&](int buf) {
        uint32_t* Kb = sm_u + buf * (2 * 64 * SMS);
        uint32_t* Vb = Kb + 64 * SMS;
        #pragma unroll
        for (int j = 0; j < 8; j++) {
            const int i = tid + j * 128;
            const int row = i >> 4, cc = (i & 15) << 2;
            *(uint4*)&Kb[row * SMS + cc] = kpre[j];
            const int d = i & 63, r4 = (i >> 6) << 2;
            *(uint4*)&Vb[d * SMS + r4] = vpre[j];
        }
    };

    // prologue: tile n0 staged into buf0; tile n0+1 prefetched into regs
    prefetch(n0 * 64);
    stage(0);
    if (n0 < n1) prefetch((n0 + 1) * 64);
    __syncthreads();

    float O[8][4] = {};
    float m0 = -CUDART_INF_F, m1 = -CUDART_INF_F;
    float l0 = 0.f, l1 = 0.f;

    for (int nblk = n0; nblk <= n1; nblk++) {
        const int cb = (nblk - n0) & 1;
        uint32_t* Ks = sm_u + cb * (2 * 64 * SMS);
        uint32_t* Vt = Ks + 64 * SMS;

        // ----- scores S = Q K^T (reads Ks, staged last iteration) -----
        float s[8][4] = {};
        #pragma unroll
        for (int nt = 0; nt < 8; nt++) {
            #pragma unroll
            for (int kt = 0; kt < 8; kt++) {
                uint32_t b0 = Ks[(nt * 8 + g) * SMS + kt * 8 + qd];
                uint32_t b1 = Ks[(nt * 8 + g) * SMS + kt * 8 + qd + 4];
                mma_tf32(s[nt][0], s[nt][1], s[nt][2], s[nt][3],
                         qa[kt][0], qa[kt][1], qa[kt][2], qa[kt][3], b0, b1);
            }
        }

        // stage tile n+1 (regs already hold it) into the other buffer;
        // then prefetch tile n+2 (latency hidden until next iteration).
        if (nblk < n1) stage(cb ^ 1);
        if (nblk + 2 <= n1) prefetch((nblk + 2) * 64);

        // causal mask on diagonal tile
        if (nblk == mblk) {
            const int r0 = mr + g, r1 = mr + g + 8;
            #pragma unroll
            for (int nt = 0; nt < 8; nt++) {
                int c = nt * 8 + 2 * qd;
                if (c     > r0) s[nt][0] = -CUDART_INF_F;
                if (c + 1 > r0) s[nt][1] = -CUDART_INF_F;
                if (c     > r1) s[nt][2] = -CUDART_INF_F;
                if (c + 1 > r1) s[nt][3] = -CUDART_INF_F;
            }
        }

        // ----- online softmax -----
        float rm0 = -CUDART_INF_F, rm1 = -CUDART_INF_F;
        #pragma unroll
        for (int nt = 0; nt < 8; nt++) {
            rm0 = fmaxf(rm0, fmaxf(s[nt][0], s[nt][1]));
            rm1 = fmaxf(rm1, fmaxf(s[nt][2], s[nt][3]));
        }
        rm0 = fmaxf(rm0, __shfl_xor_sync(0xffffffffu, rm0, 1));
        rm0 = fmaxf(rm0, __shfl_xor_sync(0xffffffffu, rm0, 2));
        rm1 = fmaxf(rm1, __shfl_xor_sync(0xffffffffu, rm1, 1));
        rm1 = fmaxf(rm1, __shfl_xor_sync(0xffffffffu, rm1, 2));

        float mn0 = fmaxf(m0, rm0);
        float mn1 = fmaxf(m1, rm1);
        float al0 = fast_ex2((m0 - mn0) * SC);
        float al1 = fast_ex2((m1 - mn1) * SC);
        m0 = mn0; m1 = mn1;

        float rs0 = 0.f, rs1 = 0.f;
        #pragma unroll
        for (int nt = 0; nt < 8; nt++) {
            float p00 = fast_ex2((s[nt][0] - mn0) * SC);
            float p01 = fast_ex2((s[nt][1] - mn0) * SC);
            float p10 = fast_ex2((s[nt][2] - mn1) * SC);
            float p11 = fast_ex2((s[nt][3] - mn1) * SC);
            rs0 += p00 + p01;
            rs1 += p10 + p11;
            s[nt][0] = p00; s[nt][1] = p01;   // keep P in C-frag registers
            s[nt][2] = p10; s[nt][3] = p11;
        }
        rs0 += __shfl_xor_sync(0xffffffffu, rs0, 1);
        rs0 += __shfl_xor_sync(0xffffffffu, rs0, 2);
        rs1 += __shfl_xor_sync(0xffffffffu, rs1, 1);
        rs1 += __shfl_xor_sync(0xffffffffu, rs1, 2);
        l0 = l0 * al0 + rs0;
        l1 = l1 * al1 + rs1;

        #pragma unroll
        for (int nt = 0; nt < 8; nt++) {
            O[nt][0] *= al0; O[nt][1] *= al0;
            O[nt][2] *= al1; O[nt][3] *= al1;
        }

        // ----- O += P V : A-frags of P built by warp shuffle -----
        // A(g, kt*8+qd) lives in C-frag word c0/c1 of lane g*4+(qd>>1)
        // (parity of qd selects the word); +2 lanes for the qd+4 column.
        const int src0 = g * 4 + (qd >> 1);
        const int src1 = src0 + 2;
        const bool odd = qd & 1;
        #pragma unroll
        for (int kt = 0; kt < 8; kt++) {
            float t0 = __shfl_sync(0xffffffffu, s[kt][0], src0);
            float t1 = __shfl_sync(0xffffffffu, s[kt][1], src0);
            float t2 = __shfl_sync(0xffffffffu, s[kt][2], src0);
            float t3 = __shfl_sync(0xffffffffu, s[kt][3], src0);
            float u0 = __shfl_sync(0xffffffffu, s[kt][0], src1);
            float u1 = __shfl_sync(0xffffffffu, s[kt][1], src1);
            float u2 = __shfl_sync(0xffffffffu, s[kt][2], src1);
            float u3 = __shfl_sync(0xffffffffu, s[kt][3], src1);
            uint32_t pa0 = f2tf32(odd ? t1 : t0);  // row g,   col kt*8+qd
            uint32_t pa1 = f2tf32(odd ? t3 : t2);  // row g+8, col kt*8+qd
            uint32_t pa2 = f2tf32(odd ? u1 : u0);  // row g,   col kt*8+qd+4
            uint32_t pa3 = f2tf32(odd ? u3 : u2);  // row g+8, col kt*8+qd+4
            #pragma unroll
            for (int nt = 0; nt < 8; nt++) {
                uint32_t b0 = Vt[(nt * 8 + g) * SMS + kt * 8 + qd];
                uint32_t b1 = Vt[(nt * 8 + g) * SMS + kt * 8 + qd + 4];
                mma_tf32(O[nt][0], O[nt][1], O[nt][2], O[nt][3],
                         pa0, pa1, pa2, pa3, b0, b1);
            }
        }

        // single barrier per tile: all warps done reading buf(cb) and done
        // staging buf(cb^1) before the next iteration touches them.
        __syncthreads();
    }

    // ----- write partials -----
    const int pbase = (mblk * MAX_CHUNKS + chunk) * 64;
    const int r0 = mr + g, r1 = mr + g + 8;
    #pragma unroll
    for (int nt = 0; nt < 8; nt++) {
        float* o0 = &g_Op[(pbase + r0) * 64 + nt * 8 + 2 * qd];
        float* o1 = &g_Op[(pbase + r1) * 64 + nt * 8 + 2 * qd];
        *(float2*)o0 = make_float2(O[nt][0], O[nt][1]);
        *(float2*)o1 = make_float2(O[nt][2], O[nt][3]);
    }
    if (qd == 0) {
        g_m[pbase + r0] = m0;  g_m[pbase + r1] = m1;
        g_l[pbase + r0] = l0;  g_l[pbase + r1] = l1;
    }
}

// ---------------------------------------------------------------------------
// Kernel 3: combine split-K partials.  grid = 128 qblocks, 128 threads.
// ---------------------------------------------------------------------------
__global__ __launch_bounds__(128) void attn_reduce_kernel(float* __restrict__ out)
{
    const int qblk = blockIdx.x;
    const int nch  = qblk / CHUNK_TILES + 1;
    const int tid  = threadIdx.x;
    const int r    = tid >> 1;
    const int c0   = (tid & 1) * 32;
    const float SC = 0.125f * 1.4426950408889634f;

    const int pbase = qblk * MAX_CHUNKS * 64;

    float mv[MAX_CHUNKS];
    float M = -CUDART_INF_F;
    for (int i = 0; i < nch; i++) {
        mv[i] = g_m[pbase + i * 64 + r];
        M = fmaxf(M, mv[i]);
    }

    float acc[32];
    #pragma unroll
    for (int j = 0; j < 32; j++) acc[j] = 0.f;
    float wl = 0.f;

    for (int i = 0; i < nch; i++) {
        float w = fast_ex2((mv[i] - M) * SC);
        wl += w * g_l[pbase + i * 64 + r];
        const float* Op = &g_Op[(pbase + i * 64 + r) * 64 + c0];
        #pragma unroll
        for (int j4 = 0; j4 < 8; j4++) {
            float4 v = *(const float4*)&Op[j4 * 4];
            acc[j4 * 4 + 0] += w * v.x;
            acc[j4 * 4 + 1] += w * v.y;
            acc[j4 * 4 + 2] += w * v.z;
            acc[j4 * 4 + 3] += w * v.w;
        }
    }

    const float inv = 1.0f / wl;
    float* o = &out[(qblk * 64 + r) * D_OUT + c0];
    #pragma unroll
    for (int j4 = 0; j4 < 8; j4++) {
        *(float4*)&o[j4 * 4] = make_float4(acc[j4 * 4 + 0] * inv,
                                           acc[j4 * 4 + 1] * inv,
                                           acc[j4 * 4 + 2] * inv,
                                           acc[j4 * 4 + 3] * inv);
    }
}

// ---------------------------------------------------------------------------
extern "C" void kernel_launch(void* const* d_in, const int* in_sizes, int n_in,
                              void* d_out, int out_size)
{
    const float* x  = (const float*)d_in[0];
    const float* Wq = (const float*)d_in[1];
    const float* Wk = (const float*)d_in[2];
    const float* Wv = (const float*)d_in[3];
    float* out = (float*)d_out;

    const int proj_smem = (128 + 64) * SMS * 4;  // 52224 bytes
    const int attn_smem = 4 * 64 * SMS * 4;      // 69632 bytes (2x double-buffered K,Vt)
    cudaFuncSetAttribute(qkv_proj_tc_kernel,
                         cudaFuncAttributeMaxDynamicSharedMemorySize, proj_smem);
    cudaFuncSetAttribute(attn_chunk_kernel,
                         cudaFuncAttributeMaxDynamicSharedMemorySize, attn_smem);

    dim3 g1(S_LEN / 128, 3);
    qkv_proj_tc_kernel<<<g1, 256, proj_smem>>>(x, Wq, Wk, Wv);
    dim3 g2(MAX_CHUNKS, S_LEN / 64);
    attn_chunk_kernel<<<g2, 128, attn_smem>>>();
    attn_reduce_kernel<<<S_LEN / 64, 128>>>(out);
}